// round 15
// baseline (speedup 1.0000x reference)
#include <cuda_runtime.h>
#include <cuda_bf16.h>
#include <cstring>

// Problem constants
#define B_   64
#define NE_  40000
#define NR_  500
#define D1_  200
#define D2_  200
#define L_   64
#define KSPLIT 200         // one partial per k2
#define LOG2E 1.4426950408889634f
#define NKS   14
#define KCHUNK 112
#define EPADK 120
#define WSTRIDE 216
#define WPLANE  (16 * WSTRIDE)
#define WBUFB   (2 * WPLANE * 2)
#define NPROD 200
#define NRED  13

typedef unsigned int u32t;

// ---------------- scratch (device globals; no allocation) ----------------
__device__ __align__(16) float g_x0T[D1_ * B_];
__device__ __align__(16) float g_rT [D2_ * B_];
__device__ __align__(16) float g_aT [L_ * B_];
__device__ __align__(16) float g_wT [L_ * B_];
__device__ __align__(16) float g_negk[L_];
__device__ __align__(16) float g_ypart[KSPLIT * D1_ * B_];
__device__ __align__(16) uint4 g_Afrag[2 * NKS * 4 * 32];
__device__ int g_done;
__device__ int g_flag2;

__device__ __forceinline__ float ex2f(float x) {
    float r; asm("ex2.approx.ftz.f32 %0, %1;" : "=f"(r) : "f"(x)); return r;
}
__device__ __forceinline__ float rcpf(float x) {
    float r; asm("rcp.approx.ftz.f32 %0, %1;" : "=f"(r) : "f"(x)); return r;
}
__device__ __forceinline__ u32t pkbf(float x, float y) {
    __nv_bfloat162 h = __floats2bfloat162_rn(x, y);
    u32t r; memcpy(&r, &h, 4); return r;
}
__device__ __forceinline__ void mma16816(float4& c, uint4 a, u32t b0, u32t b1) {
    asm volatile(
        "mma.sync.aligned.m16n8k16.row.col.f32.bf16.bf16.f32 "
        "{%0,%1,%2,%3}, {%4,%5,%6,%7}, {%8,%9}, {%0,%1,%2,%3};"
        : "+f"(c.x), "+f"(c.y), "+f"(c.z), "+f"(c.w)
        : "r"(a.x), "r"(a.y), "r"(a.z), "r"(a.w), "r"(b0), "r"(b1));
}
__device__ __forceinline__ void ldmx2t(u32t& r0, u32t& r1, u32t addr) {
    asm volatile("ldmatrix.sync.aligned.m8n8.x2.trans.shared.b16 {%0,%1}, [%2];"
                 : "=r"(r0), "=r"(r1) : "r"(addr));
}
__device__ __forceinline__ void barnamed(int id, int cnt) {
    asm volatile("bar.sync %0, %1;" :: "r"(id), "r"(cnt) : "memory");
}
__device__ __forceinline__ u32t smem_u32(const void* p) {
    u32t a; asm("{ .reg .u64 t; cvta.to.shared.u64 t, %1; cvt.u32.u64 %0, t; }"
                : "=r"(a) : "l"(p));
    return a;
}
__device__ __forceinline__ int ldacq(const int* p) {
    int v; asm volatile("ld.acquire.gpu.b32 %0, [%1];" : "=r"(v) : "l"(p));
    return v;
}

// ---------------- kernel 1: parallel gather + BN0 + branch prep + flag reset ----------------
__global__ void k_prep(const int* __restrict__ e1_idx, const int* __restrict__ r_idx,
                       const float* __restrict__ E, const float* __restrict__ R,
                       const float* __restrict__ lits, const float* __restrict__ c,
                       const float* __restrict__ var_l, const float* __restrict__ nf,
                       const float* __restrict__ g0, const float* __restrict__ b0) {
    int blk = blockIdx.x;
    int t = threadIdx.x;
    if (blk < 25) {
        __shared__ int se1[B_];
        if (t < B_) se1[t] = e1_idx[t];
        __syncthreads();
        int j    = blk * 8 + (t >> 5);
        int lane = t & 31;
        float v0 = E[(long)se1[lane] * D1_ + j];
        float v1 = E[(long)se1[lane + 32] * D1_ + j];
        float s = v0 + v1, q = v0 * v0 + v1 * v1;
#pragma unroll
        for (int off = 16; off >= 1; off >>= 1) {
            s += __shfl_xor_sync(0xffffffffu, s, off);
            q += __shfl_xor_sync(0xffffffffu, q, off);
        }
        float mu  = s * (1.f / B_);
        float var = q * (1.f / B_) - mu * mu;
        float sc  = g0[j] * rsqrtf(var + 1e-5f);
        float be  = b0[j];
        g_x0T[j * B_ + lane]      = (v0 - mu) * sc + be;
        g_x0T[j * B_ + 32 + lane] = (v1 - mu) * sc + be;
    } else if (blk < 27) {
        __shared__ int sr[B_];
        if (t < B_) sr[t] = r_idx[t];
        __syncthreads();
        int base = (blk - 25) * (D2_ * B_ / 2);
        for (int idx = t; idx < D2_ * B_ / 2; idx += 256) {
            int k = (base + idx) >> 6, b = (base + idx) & 63;
            g_rT[base + idx] = R[(long)sr[b] * D2_ + k];
        }
    } else {
        __shared__ int se1[B_], sr[B_];
        if (t < B_) { se1[t] = e1_idx[t]; sr[t] = r_idx[t]; }
        __syncthreads();
        if (t == 0) { g_done = 0; g_flag2 = 0; }
        if (t < L_) g_negk[t] = -sqrtf(LOG2E / var_l[t]);
        for (int idx = t; idx < B_ * L_; idx += 256) {
            int b = idx & 63, l = idx >> 6;
            float ks = sqrtf(LOG2E / var_l[l]);
            g_aT[l * B_ + b] = (lits[(long)se1[b] * L_ + l] - c[l]) * ks;
            g_wT[l * B_ + b] = nf[(long)sr[b] * L_ + l];
        }
    }
}

// ---------------- kernel 2: FUSED producer(wgemm) / reducer(BN1+afrag) / score ----------------
// grid 825: bid<200 producers (one k2 each); bid>=200 consumers (64 n each).
// Consumer warps 0-3: [reducers: slice reduce+BN1+afrag] spin flag -> score_l mma.
// Consumer warps 4-7: KBLN immediately (no dependency on producers).
__global__ __launch_bounds__(256) void k_main(
    const float* __restrict__ W, const float* __restrict__ E,
    const float* __restrict__ lits, const float* __restrict__ g1,
    const float* __restrict__ b1, float* __restrict__ out) {

    __shared__ __align__(16) char sbuf[D1_ * 68 * 4];   // 54400 B union

    int bid  = blockIdx.x;
    int t    = threadIdx.x;
    int lane = t & 31;
    int warp = t >> 5;

    if (bid < NPROD) {
        // ================= PRODUCER: W contraction (R14-validated) =================
        float* sOut = (float*)sbuf;
        int k2   = bid;
        int mt   = warp & 3;
        int nh   = warp >> 2;
        int ntiles = nh ? 12 : 13;
        int jbase  = nh * 104;
        int r0   = mt * 16 + (lane >> 2);

        float rv0 = g_rT[k2 * B_ + r0];
        float rv1 = g_rT[k2 * B_ + r0 + 8];
        const float* Wk = W + (long)k2 * (D1_ * D1_);
        u32t sb32 = smem_u32(sbuf);
        u32t rowoff = (lane & 15) * (WSTRIDE * 2);

        float4 acc[13];
#pragma unroll
        for (int u = 0; u < 13; u++) acc[u] = make_float4(0.f, 0.f, 0.f, 0.f);

        #define WSTAGE(st, p) {                                                   \
            int i0_ = (st) * 16;                                                  \
            __nv_bfloat16* bh = (__nv_bfloat16*)(sbuf + (p) * WBUFB);             \
            __nv_bfloat16* bl = bh + WPLANE;                                      \
            for (int q = t; q < 16 * 50; q += 256) {                              \
                int il = q / 50, j4 = (q % 50) * 4;                               \
                int i  = i0_ + il;                                                \
                float4 w = (i < D1_) ? *(const float4*)&Wk[i * D1_ + j4]          \
                                     : make_float4(0.f, 0.f, 0.f, 0.f);           \
                float h0 = __bfloat162float(__float2bfloat16_rn(w.x));            \
                float h1 = __bfloat162float(__float2bfloat16_rn(w.y));            \
                float h2 = __bfloat162float(__float2bfloat16_rn(w.z));            \
                float h3 = __bfloat162float(__float2bfloat16_rn(w.w));            \
                *(u32t*)&bh[il * WSTRIDE + j4]     = pkbf(h0, h1);                \
                *(u32t*)&bh[il * WSTRIDE + j4 + 2] = pkbf(h2, h3);                \
                *(u32t*)&bl[il * WSTRIDE + j4]     = pkbf(w.x - h0, w.y - h1);    \
                *(u32t*)&bl[il * WSTRIDE + j4 + 2] = pkbf(w.z - h2, w.w - h3);    \
            }                                                                     \
        }

        WSTAGE(0, 0);
#pragma unroll 1
        for (int st = 0; st < 13; st++) {
            __syncthreads();
            if (st < 12) WSTAGE(st + 1, (st + 1) & 1);
            int p  = st & 1;
            int i0 = st * 16;
            int c0 = i0 + 2 * (lane & 3);
            float zh[2][4], zl[2][4];
#pragma unroll
            for (int rr = 0; rr < 2; rr++) {
                int r = r0 + rr * 8;
                float rv = rr ? rv1 : rv0;
#pragma unroll
                for (int cc = 0; cc < 4; cc++) {
                    int ci = c0 + (cc & 1) + (cc >> 1) * 8;
                    float x = (ci < D1_) ? g_x0T[ci * B_ + r] : 0.f;
                    float z = rv * x;
                    float h = __bfloat162float(__float2bfloat16_rn(z));
                    zh[rr][cc] = h;
                    zl[rr][cc] = z - h;
                }
            }
            uint4 AH, AL;
            AH.x = pkbf(zh[0][0], zh[0][1]); AH.y = pkbf(zh[1][0], zh[1][1]);
            AH.z = pkbf(zh[0][2], zh[0][3]); AH.w = pkbf(zh[1][2], zh[1][3]);
            AL.x = pkbf(zl[0][0], zl[0][1]); AL.y = pkbf(zl[1][0], zl[1][1]);
            AL.z = pkbf(zl[0][2], zl[0][3]); AL.w = pkbf(zl[1][2], zl[1][3]);

            u32t hibase = sb32 + p * WBUFB + rowoff;
#pragma unroll
            for (int tile = 0; tile < 13; tile++) {
                if (tile >= ntiles) break;
                int nj = jbase + tile * 8;
                u32t bh0, bh1, bl0, bl1;
                ldmx2t(bh0, bh1, hibase + nj * 2);
                ldmx2t(bl0, bl1, hibase + WPLANE * 2 + nj * 2);
                mma16816(acc[tile], AH, bh0, bh1);
                mma16816(acc[tile], AH, bl0, bl1);
                mma16816(acc[tile], AL, bh0, bh1);
            }
        }
        #undef WSTAGE

        __syncthreads();
        {
            int cc0 = 2 * (lane & 3);
#pragma unroll
            for (int tile = 0; tile < 13; tile++) {
                if (tile >= ntiles) break;
                int cj = jbase + tile * 8 + cc0;
                sOut[cj * 68 + r0]           = acc[tile].x;
                sOut[(cj + 1) * 68 + r0]     = acc[tile].y;
                sOut[cj * 68 + r0 + 8]       = acc[tile].z;
                sOut[(cj + 1) * 68 + r0 + 8] = acc[tile].w;
            }
        }
        __syncthreads();
        float* yp = g_ypart + (long)k2 * (D1_ * B_);
        for (int q = t; q < D1_ * 16; q += 256) {
            int j = q >> 4, b4 = (q & 15) * 4;
            *(float4*)&yp[j * B_ + b4] = *(const float4*)&sOut[j * 68 + b4];
        }
        __threadfence();
        __syncthreads();
        if (t == 0) atomicAdd(&g_done, 1);
        return;
    }

    // ================= CONSUMER =================
    int bid2 = bid - NPROD;
    int n0   = bid2 * 64;

    __nv_bfloat16* eb = (__nv_bfloat16*)sbuf;                       // [0, 30720)
    float (*scores)[76] = (float (*)[76])sbuf;
    float (*Ssn)[68] = (float (*)[68])(sbuf + 30720);               // [30720, 48128)
    float* rx1   = (float*)(sbuf + 48128);                          // [48128, 52224) 16x64
    float* rstat = (float*)(sbuf + 52224);                          // 32 floats

    if (warp < 4) {
        // ---- mma group: threads 0..127 ----
        if (bid2 < NRED) {
            // reducer slice s = bid2: wait for all producers, then reduce+BN1+afrag
            int s = bid2;
            if (t == 0) { while (ldacq(&g_done) < NPROD) __nanosleep(128); }
            barnamed(1, 128);
            for (int idx = t; idx < 16 * 64; idx += 128) {
                int jl = idx >> 6, b = idx & 63;
                const float* bp = g_ypart + (s * 16 + jl) * B_ + b;
                float a0 = 0.f, a1 = 0.f, a2 = 0.f, a3 = 0.f;
#pragma unroll 2
                for (int ks = 0; ks < KSPLIT; ks += 4) {
                    a0 += bp[(long)ks * (D1_ * B_)];
                    a1 += bp[(long)(ks + 1) * (D1_ * B_)];
                    a2 += bp[(long)(ks + 2) * (D1_ * B_)];
                    a3 += bp[(long)(ks + 3) * (D1_ * B_)];
                }
                rx1[idx] = (a0 + a1) + (a2 + a3);
            }
            barnamed(1, 128);
            if (t < 16) {
                int j = s * 16 + t;
                float s1 = 0.f, s2 = 0.f;
#pragma unroll 8
                for (int b = 0; b < B_; b++) {
                    float v = rx1[t * 64 + b];
                    s1 += v; s2 += v * v;
                }
                float mu  = s1 * (1.f / B_);
                float var = s2 * (1.f / B_) - mu * mu;
                float sc  = g1[j] * rsqrtf(var + 1e-5f);
                rstat[2 * t]     = sc;
                rstat[2 * t + 1] = b1[j] - mu * sc;
            }
            barnamed(1, 128);
            for (int idx = t; idx < 16 * 64; idx += 128) {
                int jl = idx >> 6;
                rx1[idx] = rx1[idx] * rstat[2 * jl] + rstat[2 * jl + 1];
            }
            barnamed(1, 128);
            {   // afrag for ks = s, mt = warp
                int mt = warp;
                int r0 = mt * 16 + (lane >> 2);
                int c0 = 2 * (lane & 3);
                float vh[2][4], vl[2][4];
#pragma unroll
                for (int rr = 0; rr < 2; rr++) {
                    int r = r0 + rr * 8;
#pragma unroll
                    for (int cc = 0; cc < 4; cc++) {
                        int cl = c0 + (cc & 1) + (cc >> 1) * 8;
                        float x = rx1[cl * 64 + r];
                        float h = __bfloat162float(__float2bfloat16_rn(x));
                        vh[rr][cc] = h;
                        vl[rr][cc] = x - h;
                    }
                }
                uint4 H, L;
                H.x = pkbf(vh[0][0], vh[0][1]); H.y = pkbf(vh[1][0], vh[1][1]);
                H.z = pkbf(vh[0][2], vh[0][3]); H.w = pkbf(vh[1][2], vh[1][3]);
                L.x = pkbf(vl[0][0], vl[0][1]); L.y = pkbf(vl[1][0], vl[1][1]);
                L.z = pkbf(vl[0][2], vl[0][3]); L.w = pkbf(vl[1][2], vl[1][3]);
                int base = (s * 4 + mt) * 32 + lane;
                g_Afrag[base]                = H;
                g_Afrag[base + NKS * 4 * 32] = L;
            }
            __threadfence();
            barnamed(1, 128);
            if (t == 0) atomicAdd(&g_flag2, 1);
        }
        // wait for all afrag slices (reducer blocks included)
        if (t == 0) { while (ldacq(&g_flag2) < NRED) __nanosleep(128); }
        barnamed(1, 128);

        // ---- score_l via bf16 hi/lo mma (R14-validated) ----
        int mt = warp;
        float4 acc[8];
#pragma unroll
        for (int u = 0; u < 8; u++) acc[u] = make_float4(0.f, 0.f, 0.f, 0.f);

#pragma unroll 1
        for (int chunk = 0; chunk < 2; chunk++) {
            int kb = chunk * KCHUNK;
            for (int idx = t; idx < 64 * (KCHUNK / 4); idx += 128) {
                int row = idx / (KCHUNK / 4);
                int kq  = (idx % (KCHUNK / 4)) * 4;
                int kg  = kb + kq;
                float v0, v1, v2, v3;
                if (kg + 3 < D1_) {
                    float4 v = *(const float4*)&E[(long)(n0 + row) * D1_ + kg];
                    v0 = v.x; v1 = v.y; v2 = v.z; v3 = v.w;
                } else {
                    v0 = (kg     < D1_) ? E[(long)(n0 + row) * D1_ + kg]     : 0.f;
                    v1 = (kg + 1 < D1_) ? E[(long)(n0 + row) * D1_ + kg + 1] : 0.f;
                    v2 = (kg + 2 < D1_) ? E[(long)(n0 + row) * D1_ + kg + 2] : 0.f;
                    v3 = (kg + 3 < D1_) ? E[(long)(n0 + row) * D1_ + kg + 3] : 0.f;
                }
                float h0 = __bfloat162float(__float2bfloat16_rn(v0));
                float h1 = __bfloat162float(__float2bfloat16_rn(v1));
                float h2 = __bfloat162float(__float2bfloat16_rn(v2));
                float h3 = __bfloat162float(__float2bfloat16_rn(v3));
                *(u32t*)&eb[row * EPADK + kq]            = pkbf(h0, h1);
                *(u32t*)&eb[row * EPADK + kq + 2]        = pkbf(h2, h3);
                *(u32t*)&eb[(64 + row) * EPADK + kq]     = pkbf(v0 - h0, v1 - h1);
                *(u32t*)&eb[(64 + row) * EPADK + kq + 2] = pkbf(v2 - h2, v3 - h3);
            }
            barnamed(1, 128);
            int kslim = chunk ? 6 : 7;
#pragma unroll 1
            for (int ksl = 0; ksl < kslim; ksl++) {
                int ks = chunk * 7 + ksl;
                uint4 AH = g_Afrag[(ks * 4 + mt) * 32 + lane];
                uint4 AL = g_Afrag[(ks * 4 + mt) * 32 + lane + NKS * 4 * 32];
                int kloc = ksl * 16 + 2 * (lane & 3);
#pragma unroll
                for (int tile = 0; tile < 8; tile++) {
                    int n = tile * 8 + (lane >> 2);
                    u32t bh0 = *(const u32t*)&eb[n * EPADK + kloc];
                    u32t bh1 = *(const u32t*)&eb[n * EPADK + kloc + 8];
                    u32t bl0 = *(const u32t*)&eb[(64 + n) * EPADK + kloc];
                    u32t bl1 = *(const u32t*)&eb[(64 + n) * EPADK + kloc + 8];
                    mma16816(acc[tile], AH, bh0, bh1);
                    mma16816(acc[tile], AH, bl0, bl1);
                    mma16816(acc[tile], AL, bh0, bh1);
                }
            }
            barnamed(1, 128);
        }
        {
            int sr = mt * 16 + (lane >> 2);
            int sc = 2 * (lane & 3);
#pragma unroll
            for (int tile = 0; tile < 8; tile++) {
                *(float2*)&scores[sr][sc + tile * 8]     = make_float2(acc[tile].x, acc[tile].y);
                *(float2*)&scores[sr + 8][sc + tile * 8] = make_float2(acc[tile].z, acc[tile].w);
            }
        }
        __syncthreads();
    } else {
        // ---- KBLN group: threads 128..255 — starts immediately ----
        int tl = t - 128;
        for (int i = tl; i < 64 * 64; i += 128) {
            int l = i & 63, nl = i >> 6;
            Ssn[l][nl] = lits[(long)(n0 + nl) * L_ + l] * g_negk[l];
        }
        barnamed(2, 128);

        int nbase = (warp - 4) * 16;
        float acc0[16], acc1[16];
#pragma unroll
        for (int u = 0; u < 16; u++) { acc0[u] = 0.f; acc1[u] = 0.f; }

        const float2* aT2 = (const float2*)g_aT;
        const float2* wT2 = (const float2*)g_wT;
#pragma unroll 1
        for (int lc = 0; lc < 16; lc++) {
            int l0 = lc * 4;
            float2 a2[4], w2[4];
#pragma unroll
            for (int u = 0; u < 4; u++) {
                a2[u] = aT2[(l0 + u) * 32 + lane];
                w2[u] = wT2[(l0 + u) * 32 + lane];
            }
#pragma unroll
            for (int u = 0; u < 4; u++) {
                float4 svA = *(const float4*)&Ssn[l0 + u][nbase];
                float4 svB = *(const float4*)&Ssn[l0 + u][nbase + 4];
                float4 svC = *(const float4*)&Ssn[l0 + u][nbase + 8];
                float4 svD = *(const float4*)&Ssn[l0 + u][nbase + 12];
                float sv[16] = {svA.x, svA.y, svA.z, svA.w, svB.x, svB.y, svB.z, svB.w,
                                svC.x, svC.y, svC.z, svC.w, svD.x, svD.y, svD.z, svD.w};
#pragma unroll
                for (int nn = 0; nn < 16; nn++) {
                    float d0 = a2[u].x + sv[nn];
                    float d1 = a2[u].y + sv[nn];
                    acc0[nn] += w2[u].x * ex2f(-d0 * d0);
                    acc1[nn] += w2[u].y * ex2f(-d1 * d1);
                }
            }
        }
        __syncthreads();   // join: score_l ready in smem

        int b0r = 2 * lane, b1r = b0r + 1;
#pragma unroll
        for (int g = 0; g < 4; g++) {
            float4 s0 = *(const float4*)&scores[b0r][nbase + g * 4];
            float4 s1 = *(const float4*)&scores[b1r][nbase + g * 4];
            float o0x = rcpf(1.f + ex2f(-LOG2E * (s0.x + acc0[g * 4 + 0])));
            float o0y = rcpf(1.f + ex2f(-LOG2E * (s0.y + acc0[g * 4 + 1])));
            float o0z = rcpf(1.f + ex2f(-LOG2E * (s0.z + acc0[g * 4 + 2])));
            float o0w = rcpf(1.f + ex2f(-LOG2E * (s0.w + acc0[g * 4 + 3])));
            float o1x = rcpf(1.f + ex2f(-LOG2E * (s1.x + acc1[g * 4 + 0])));
            float o1y = rcpf(1.f + ex2f(-LOG2E * (s1.y + acc1[g * 4 + 1])));
            float o1z = rcpf(1.f + ex2f(-LOG2E * (s1.z + acc1[g * 4 + 2])));
            float o1w = rcpf(1.f + ex2f(-LOG2E * (s1.w + acc1[g * 4 + 3])));
            int n = n0 + nbase + g * 4;
            *(float4*)&out[(long)b0r * NE_ + n] = make_float4(o0x, o0y, o0z, o0w);
            *(float4*)&out[(long)b1r * NE_ + n] = make_float4(o1x, o1y, o1z, o1w);
        }
    }
}

// ---------------- launch ----------------
extern "C" void kernel_launch(void* const* d_in, const int* in_sizes, int n_in,
                              void* d_out, int out_size) {
    const int*   e1_idx = (const int*)  d_in[0];
    const int*   r_idx  = (const int*)  d_in[1];
    const float* E      = (const float*)d_in[2];
    const float* R      = (const float*)d_in[3];
    const float* W      = (const float*)d_in[4];
    const float* lits   = (const float*)d_in[5];
    const float* c      = (const float*)d_in[6];
    const float* var_l  = (const float*)d_in[7];
    const float* nf     = (const float*)d_in[8];
    const float* g0     = (const float*)d_in[9];
    const float* b0     = (const float*)d_in[10];
    const float* g1     = (const float*)d_in[11];
    const float* b1     = (const float*)d_in[12];
    float* out = (float*)d_out;

    k_prep<<<28, 256>>>(e1_idx, r_idx, E, R, lits, c, var_l, nf, g0, b0);
    k_main<<<NPROD + NE_ / 64, 256>>>(W, E, lits, g1, b1, out);
}

// round 17
// speedup vs baseline: 1.5959x; 1.5959x over previous
#include <cuda_runtime.h>
#include <cuda_bf16.h>
#include <cstring>

// Problem constants
#define B_   64
#define NE_  40000
#define NR_  500
#define D1_  200
#define D2_  200
#define L_   64
#define KSPLIT 200         // one partial slice per k2
#define LOG2E 1.4426950408889634f
#define NKS   14           // score path: K padded to 224
#define KCHUNK 112
#define EPADK 120
// wgemm j-half staging: 104 bf16 per row (208B, 16B-aligned rows for ldmatrix)
#define WST   104
#define WPLANE (16 * WST)               // bf16 per plane
#define WBUFB  (2 * WPLANE * 2)         // bytes per buffer (hi+lo) = 6656

typedef unsigned int u32t;

// ---------------- scratch (device globals; no allocation) ----------------
__device__ __align__(16) float g_x0T[D1_ * B_];          // [i][b]
__device__ __align__(16) float g_rT [D2_ * B_];          // [k][b]
__device__ __align__(16) float g_aT [L_ * B_];           // [l][b]
__device__ __align__(16) float g_wT [L_ * B_];           // [l][b]
__device__ __align__(16) float g_negk[L_];               // -sqrt(log2e/var_l)
__device__ __align__(16) float g_ypart[KSPLIT * D1_ * B_];
__device__ __align__(16) uint4 g_Afrag[2 * NKS * 4 * 32];

__device__ __forceinline__ float ex2f(float x) {
    float r; asm("ex2.approx.ftz.f32 %0, %1;" : "=f"(r) : "f"(x)); return r;
}
__device__ __forceinline__ float rcpf(float x) {
    float r; asm("rcp.approx.ftz.f32 %0, %1;" : "=f"(r) : "f"(x)); return r;
}
__device__ __forceinline__ u32t pkbf(float x, float y) {
    __nv_bfloat162 h = __floats2bfloat162_rn(x, y);
    u32t r; memcpy(&r, &h, 4); return r;
}
__device__ __forceinline__ void mma16816(float4& c, uint4 a, u32t b0, u32t b1) {
    asm volatile(
        "mma.sync.aligned.m16n8k16.row.col.f32.bf16.bf16.f32 "
        "{%0,%1,%2,%3}, {%4,%5,%6,%7}, {%8,%9}, {%0,%1,%2,%3};"
        : "+f"(c.x), "+f"(c.y), "+f"(c.z), "+f"(c.w)
        : "r"(a.x), "r"(a.y), "r"(a.z), "r"(a.w), "r"(b0), "r"(b1));
}
__device__ __forceinline__ void ldmx2t(u32t& r0, u32t& r1, u32t addr) {
    asm volatile("ldmatrix.sync.aligned.m8n8.x2.trans.shared.b16 {%0,%1}, [%2];"
                 : "=r"(r0), "=r"(r1) : "r"(addr));
}
__device__ __forceinline__ void barnamed(int id, int cnt) {
    asm volatile("bar.sync %0, %1;" :: "r"(id), "r"(cnt) : "memory");
}
__device__ __forceinline__ u32t smem_u32(const void* p) {
    u32t a; asm("{ .reg .u64 t; cvta.to.shared.u64 t, %1; cvt.u32.u64 %0, t; }"
                : "=r"(a) : "l"(p));
    return a;
}

// ---------------- kernel 1: parallel gather + BN0 + branch prep ----------------
__global__ void k_prep(const int* __restrict__ e1_idx, const int* __restrict__ r_idx,
                       const float* __restrict__ E, const float* __restrict__ R,
                       const float* __restrict__ lits, const float* __restrict__ c,
                       const float* __restrict__ var_l, const float* __restrict__ nf,
                       const float* __restrict__ g0, const float* __restrict__ b0) {
    int blk = blockIdx.x;
    int t = threadIdx.x;
    if (blk < 25) {
        __shared__ int se1[B_];
        if (t < B_) se1[t] = e1_idx[t];
        __syncthreads();
        int j    = blk * 8 + (t >> 5);
        int lane = t & 31;
        float v0 = E[(long)se1[lane] * D1_ + j];
        float v1 = E[(long)se1[lane + 32] * D1_ + j];
        float s = v0 + v1, q = v0 * v0 + v1 * v1;
#pragma unroll
        for (int off = 16; off >= 1; off >>= 1) {
            s += __shfl_xor_sync(0xffffffffu, s, off);
            q += __shfl_xor_sync(0xffffffffu, q, off);
        }
        float mu  = s * (1.f / B_);
        float var = q * (1.f / B_) - mu * mu;
        float sc  = g0[j] * rsqrtf(var + 1e-5f);
        float be  = b0[j];
        g_x0T[j * B_ + lane]      = (v0 - mu) * sc + be;
        g_x0T[j * B_ + 32 + lane] = (v1 - mu) * sc + be;
    } else if (blk < 27) {
        __shared__ int sr[B_];
        if (t < B_) sr[t] = r_idx[t];
        __syncthreads();
        int base = (blk - 25) * (D2_ * B_ / 2);
        for (int idx = t; idx < D2_ * B_ / 2; idx += 256) {
            int k = (base + idx) >> 6, b = (base + idx) & 63;
            g_rT[base + idx] = R[(long)sr[b] * D2_ + k];
        }
    } else {
        __shared__ int se1[B_], sr[B_];
        if (t < B_) { se1[t] = e1_idx[t]; sr[t] = r_idx[t]; }
        __syncthreads();
        if (t < L_) g_negk[t] = -sqrtf(LOG2E / var_l[t]);
        for (int idx = t; idx < B_ * L_; idx += 256) {
            int b = idx & 63, l = idx >> 6;
            float ks = sqrtf(LOG2E / var_l[l]);
            g_aT[l * B_ + b] = (lits[(long)se1[b] * L_ + l] - c[l]) * ks;
            g_wT[l * B_ + b] = nf[(long)sr[b] * L_ + l];
        }
    }
}

// ---------------- kernel 2: W contraction, j-split (2 halves) per k2 ----------------
// grid (2, 200): blockIdx.x = j-half h, blockIdx.y = k2. block 256 = 8 warps:
// mt = warp&3 (16 b-rows), jq = warp>>2 (quarter of this j-half).
__global__ __launch_bounds__(256) void k_wgemm(const float* __restrict__ W) {
    __shared__ __align__(16) char sbuf[28288];           // max(2*WBUFB=13312, 104*68*4)
    float* sOut = (float*)sbuf;

    int h    = blockIdx.x;            // 0: j 0..103 (13 tiles), 1: j 104..199 (12 tiles)
    int k2   = blockIdx.y;
    int t    = threadIdx.x;
    int lane = t & 31;
    int warp = t >> 5;
    int mt   = warp & 3;
    int jq   = warp >> 2;
    int jg0  = h * 104;               // global j base of this block
    int cols = h ? 96 : 104;
    int f4c  = cols >> 2;             // 24 or 26 float4 groups per row
    int NTq  = h ? 6 : (jq ? 6 : 7);  // tiles for this warp
    int jqb  = jq ? (h ? 48 : 56) : 0;
    int r0   = mt * 16 + (lane >> 2);

    float rv0 = g_rT[k2 * B_ + r0];
    float rv1 = g_rT[k2 * B_ + r0 + 8];
    const float* Wk = W + (long)k2 * (D1_ * D1_);
    u32t sb32 = smem_u32(sbuf);
    u32t rowoff = (lane & 15) * (WST * 2);

    float4 acc[7];
#pragma unroll
    for (int u = 0; u < 7; u++) acc[u] = make_float4(0.f, 0.f, 0.f, 0.f);

    // stage W rows i0..i0+15 x [jg0, jg0+cols) as bf16 hi/lo into buffer p
    #define WSTAGE(st, p) {                                                   \
        int i0_ = (st) * 16;                                                  \
        __nv_bfloat16* bh = (__nv_bfloat16*)(sbuf + (p) * WBUFB);             \
        __nv_bfloat16* bl = bh + WPLANE;                                      \
        for (int q = t; q < 16 * 26; q += 256) {                              \
            int il = q / 26, g = q % 26;                                      \
            if (g < f4c) {                                                    \
                int i  = i0_ + il;                                            \
                int j4 = g * 4;                                               \
                float4 w = (i < D1_) ? *(const float4*)&Wk[i * D1_ + jg0 + j4] \
                                     : make_float4(0.f, 0.f, 0.f, 0.f);       \
                float h0 = __bfloat162float(__float2bfloat16_rn(w.x));        \
                float h1 = __bfloat162float(__float2bfloat16_rn(w.y));        \
                float h2 = __bfloat162float(__float2bfloat16_rn(w.z));        \
                float h3 = __bfloat162float(__float2bfloat16_rn(w.w));        \
                *(u32t*)&bh[il * WST + j4]     = pkbf(h0, h1);                \
                *(u32t*)&bh[il * WST + j4 + 2] = pkbf(h2, h3);                \
                *(u32t*)&bl[il * WST + j4]     = pkbf(w.x - h0, w.y - h1);    \
                *(u32t*)&bl[il * WST + j4 + 2] = pkbf(w.z - h2, w.w - h3);    \
            }                                                                 \
        }                                                                     \
    }

    WSTAGE(0, 0);
#pragma unroll 1
    for (int st = 0; st < 13; st++) {
        __syncthreads();
        if (st < 12) WSTAGE(st + 1, (st + 1) & 1);
        int p  = st & 1;
        int i0 = st * 16;
        // A-fragment: z = rv * x0, bf16 hi/lo (validated path)
        int c0 = i0 + 2 * (lane & 3);
        float zh[2][4], zl[2][4];
#pragma unroll
        for (int rr = 0; rr < 2; rr++) {
            int r = r0 + rr * 8;
            float rv = rr ? rv1 : rv0;
#pragma unroll
            for (int cc = 0; cc < 4; cc++) {
                int ci = c0 + (cc & 1) + (cc >> 1) * 8;
                float x = (ci < D1_) ? g_x0T[ci * B_ + r] : 0.f;
                float z = rv * x;
                float hh = __bfloat162float(__float2bfloat16_rn(z));
                zh[rr][cc] = hh;
                zl[rr][cc] = z - hh;
            }
        }
        uint4 AH, AL;
        AH.x = pkbf(zh[0][0], zh[0][1]); AH.y = pkbf(zh[1][0], zh[1][1]);
        AH.z = pkbf(zh[0][2], zh[0][3]); AH.w = pkbf(zh[1][2], zh[1][3]);
        AL.x = pkbf(zl[0][0], zl[0][1]); AL.y = pkbf(zl[1][0], zl[1][1]);
        AL.z = pkbf(zl[0][2], zl[0][3]); AL.w = pkbf(zl[1][2], zl[1][3]);

        u32t hibase = sb32 + p * WBUFB + rowoff;
#pragma unroll
        for (int tile = 0; tile < 7; tile++) {
            if (tile >= NTq) break;
            int nj = jqb + tile * 8;
            u32t bh0, bh1, bl0, bl1;
            ldmx2t(bh0, bh1, hibase + nj * 2);
            ldmx2t(bl0, bl1, hibase + WPLANE * 2 + nj * 2);
            mma16816(acc[tile], AH, bh0, bh1);
            mma16816(acc[tile], AH, bl0, bl1);
            mma16816(acc[tile], AL, bh0, bh1);
        }
    }
    #undef WSTAGE

    __syncthreads();
    {
        int cc0 = 2 * (lane & 3);
#pragma unroll
        for (int tile = 0; tile < 7; tile++) {
            if (tile >= NTq) break;
            int cj = jqb + tile * 8 + cc0;     // local j
            sOut[cj * 68 + r0]           = acc[tile].x;
            sOut[(cj + 1) * 68 + r0]     = acc[tile].y;
            sOut[cj * 68 + r0 + 8]       = acc[tile].z;
            sOut[(cj + 1) * 68 + r0 + 8] = acc[tile].w;
        }
    }
    __syncthreads();
    float* yp = g_ypart + (long)k2 * (D1_ * B_) + (long)jg0 * B_;
    for (int q = t; q < cols * 16; q += 256) {
        int j = q >> 4, b4 = (q & 15) * 4;
        *(float4*)&yp[j * B_ + b4] = *(const float4*)&sOut[j * 68 + b4];
    }
}

// ---------------- kernel 3: reduce + BN1 + A-fragment build (fused) ----------------
__global__ __launch_bounds__(512) void k_bn1f(const float* __restrict__ g1,
                                              const float* __restrict__ b1) {
    __shared__ float x1s[16][64];
    int t    = threadIdx.x;
    int wid  = t >> 5;
    int lane = t & 31;
    int blk  = blockIdx.x;
    int j    = blk * 16 + wid;

    if (j < D1_) {
        float y0 = 0.f, y1 = 0.f;
#pragma unroll 8
        for (int ks = 0; ks < KSPLIT; ks++) {
            y0 += g_ypart[ks * (D1_ * B_) + j * B_ + lane];
            y1 += g_ypart[ks * (D1_ * B_) + j * B_ + 32 + lane];
        }
        float s = y0 + y1, q = y0 * y0 + y1 * y1;
#pragma unroll
        for (int off = 16; off >= 1; off >>= 1) {
            s += __shfl_xor_sync(0xffffffffu, s, off);
            q += __shfl_xor_sync(0xffffffffu, q, off);
        }
        float mu  = s * (1.f / B_);
        float var = q * (1.f / B_) - mu * mu;
        float sc  = g1[j] * rsqrtf(var + 1e-5f);
        float be  = b1[j];
        x1s[wid][lane]      = (y0 - mu) * sc + be;
        x1s[wid][lane + 32] = (y1 - mu) * sc + be;
    } else {
        x1s[wid][lane] = 0.f;
        x1s[wid][lane + 32] = 0.f;
    }
    __syncthreads();

    if (wid < 4) {
        int mt = wid;
        int r0 = mt * 16 + (lane >> 2);
        int c0 = 2 * (lane & 3);
        float vh[2][4], vl[2][4];
#pragma unroll
        for (int rr = 0; rr < 2; rr++) {
            int r = r0 + rr * 8;
#pragma unroll
            for (int cc = 0; cc < 4; cc++) {
                int cl = c0 + (cc & 1) + (cc >> 1) * 8;
                float x = x1s[cl][r];
                float h = __bfloat162float(__float2bfloat16_rn(x));
                vh[rr][cc] = h;
                vl[rr][cc] = x - h;
            }
        }
        uint4 H, L;
        H.x = pkbf(vh[0][0], vh[0][1]); H.y = pkbf(vh[1][0], vh[1][1]);
        H.z = pkbf(vh[0][2], vh[0][3]); H.w = pkbf(vh[1][2], vh[1][3]);
        L.x = pkbf(vl[0][0], vl[0][1]); L.y = pkbf(vl[1][0], vl[1][1]);
        L.z = pkbf(vl[0][2], vl[0][3]); L.w = pkbf(vl[1][2], vl[1][3]);
        int base = (blk * 4 + mt) * 32 + lane;
        g_Afrag[base]                = H;
        g_Afrag[base + NKS * 4 * 32] = L;
    }
}

// ---------------- kernel 4: warp-specialized score (R13 config: 256 thr) ----------------
// grid 625 (64 n), block 256: warps 0-3 mma score_l; warps 4-7 KBLN (16 n each).
__global__ __launch_bounds__(256) void k_score(
    const float* __restrict__ E, const float* __restrict__ lits,
    float* __restrict__ out) {

    __shared__ __align__(16) char u_buf[2 * 64 * EPADK * 2];
    __shared__ __align__(16) float Ssn[64][68];

    __nv_bfloat16* eb = (__nv_bfloat16*)u_buf;
    float (*scores)[76] = (float (*)[76])u_buf;

    int t    = threadIdx.x;
    int lane = t & 31;
    int warp = t >> 5;
    int n0   = blockIdx.x * 64;

    if (warp < 4) {
        // ---- mma group: threads 0..127 ----
        int mt = warp;
        float4 acc[8];
#pragma unroll
        for (int u = 0; u < 8; u++) acc[u] = make_float4(0.f, 0.f, 0.f, 0.f);

#pragma unroll 1
        for (int chunk = 0; chunk < 2; chunk++) {
            int kb = chunk * KCHUNK;
            for (int idx = t; idx < 64 * (KCHUNK / 4); idx += 128) {
                int row = idx / (KCHUNK / 4);
                int kq  = (idx % (KCHUNK / 4)) * 4;
                int kg  = kb + kq;
                float v0, v1, v2, v3;
                if (kg + 3 < D1_) {
                    float4 v = *(const float4*)&E[(long)(n0 + row) * D1_ + kg];
                    v0 = v.x; v1 = v.y; v2 = v.z; v3 = v.w;
                } else {
                    v0 = (kg     < D1_) ? E[(long)(n0 + row) * D1_ + kg]     : 0.f;
                    v1 = (kg + 1 < D1_) ? E[(long)(n0 + row) * D1_ + kg + 1] : 0.f;
                    v2 = (kg + 2 < D1_) ? E[(long)(n0 + row) * D1_ + kg + 2] : 0.f;
                    v3 = (kg + 3 < D1_) ? E[(long)(n0 + row) * D1_ + kg + 3] : 0.f;
                }
                float h0 = __bfloat162float(__float2bfloat16_rn(v0));
                float h1 = __bfloat162float(__float2bfloat16_rn(v1));
                float h2 = __bfloat162float(__float2bfloat16_rn(v2));
                float h3 = __bfloat162float(__float2bfloat16_rn(v3));
                *(u32t*)&eb[row * EPADK + kq]            = pkbf(h0, h1);
                *(u32t*)&eb[row * EPADK + kq + 2]        = pkbf(h2, h3);
                *(u32t*)&eb[(64 + row) * EPADK + kq]     = pkbf(v0 - h0, v1 - h1);
                *(u32t*)&eb[(64 + row) * EPADK + kq + 2] = pkbf(v2 - h2, v3 - h3);
            }
            barnamed(1, 128);
            int kslim = chunk ? 6 : 7;
#pragma unroll 1
            for (int ksl = 0; ksl < kslim; ksl++) {
                int ks = chunk * 7 + ksl;
                uint4 AH = g_Afrag[(ks * 4 + mt) * 32 + lane];
                uint4 AL = g_Afrag[(ks * 4 + mt) * 32 + lane + NKS * 4 * 32];
                int kloc = ksl * 16 + 2 * (lane & 3);
#pragma unroll
                for (int tile = 0; tile < 8; tile++) {
                    int n = tile * 8 + (lane >> 2);
                    u32t bh0 = *(const u32t*)&eb[n * EPADK + kloc];
                    u32t bh1 = *(const u32t*)&eb[n * EPADK + kloc + 8];
                    u32t bl0 = *(const u32t*)&eb[(64 + n) * EPADK + kloc];
                    u32t bl1 = *(const u32t*)&eb[(64 + n) * EPADK + kloc + 8];
                    mma16816(acc[tile], AH, bh0, bh1);
                    mma16816(acc[tile], AH, bl0, bl1);
                    mma16816(acc[tile], AL, bh0, bh1);
                }
            }
            barnamed(1, 128);
        }
        {
            int sr = mt * 16 + (lane >> 2);
            int sc = 2 * (lane & 3);
#pragma unroll
            for (int tile = 0; tile < 8; tile++) {
                *(float2*)&scores[sr][sc + tile * 8]     = make_float2(acc[tile].x, acc[tile].y);
                *(float2*)&scores[sr + 8][sc + tile * 8] = make_float2(acc[tile].z, acc[tile].w);
            }
        }
        __syncthreads();
    } else {
        // ---- KBLN group: threads 128..255 (4 warps, 16 n each) ----
        int tl = t - 128;
        for (int i = tl; i < 64 * 64; i += 128) {
            int l = i & 63, nl = i >> 6;
            Ssn[l][nl] = lits[(long)(n0 + nl) * L_ + l] * g_negk[l];
        }
        barnamed(2, 128);

        int nbase = (warp - 4) * 16;
        float acc0[16], acc1[16];
#pragma unroll
        for (int u = 0; u < 16; u++) { acc0[u] = 0.f; acc1[u] = 0.f; }

        const float2* aT2 = (const float2*)g_aT;
        const float2* wT2 = (const float2*)g_wT;
#pragma unroll 1
        for (int lc = 0; lc < 16; lc++) {
            int l0 = lc * 4;
            float2 a2[4], w2[4];
#pragma unroll
            for (int u = 0; u < 4; u++) {
                a2[u] = aT2[(l0 + u) * 32 + lane];
                w2[u] = wT2[(l0 + u) * 32 + lane];
            }
#pragma unroll
            for (int u = 0; u < 4; u++) {
                float4 svA = *(const float4*)&Ssn[l0 + u][nbase];
                float4 svB = *(const float4*)&Ssn[l0 + u][nbase + 4];
                float4 svC = *(const float4*)&Ssn[l0 + u][nbase + 8];
                float4 svD = *(const float4*)&Ssn[l0 + u][nbase + 12];
                float sv[16] = {svA.x, svA.y, svA.z, svA.w, svB.x, svB.y, svB.z, svB.w,
                                svC.x, svC.y, svC.z, svC.w, svD.x, svD.y, svD.z, svD.w};
#pragma unroll
                for (int nn = 0; nn < 16; nn++) {
                    float d0 = a2[u].x + sv[nn];
                    float d1 = a2[u].y + sv[nn];
                    acc0[nn] += w2[u].x * ex2f(-d0 * d0);
                    acc1[nn] += w2[u].y * ex2f(-d1 * d1);
                }
            }
        }
        __syncthreads();   // join: score_l in smem

        int b0r = 2 * lane, b1r = b0r + 1;
#pragma unroll
        for (int g = 0; g < 4; g++) {
            float4 s0 = *(const float4*)&scores[b0r][nbase + g * 4];
            float4 s1 = *(const float4*)&scores[b1r][nbase + g * 4];
            float o0x = rcpf(1.f + ex2f(-LOG2E * (s0.x + acc0[g * 4 + 0])));
            float o0y = rcpf(1.f + ex2f(-LOG2E * (s0.y + acc0[g * 4 + 1])));
            float o0z = rcpf(1.f + ex2f(-LOG2E * (s0.z + acc0[g * 4 + 2])));
            float o0w = rcpf(1.f + ex2f(-LOG2E * (s0.w + acc0[g * 4 + 3])));
            float o1x = rcpf(1.f + ex2f(-LOG2E * (s1.x + acc1[g * 4 + 0])));
            float o1y = rcpf(1.f + ex2f(-LOG2E * (s1.y + acc1[g * 4 + 1])));
            float o1z = rcpf(1.f + ex2f(-LOG2E * (s1.z + acc1[g * 4 + 2])));
            float o1w = rcpf(1.f + ex2f(-LOG2E * (s1.w + acc1[g * 4 + 3])));
            int n = n0 + nbase + g * 4;
            *(float4*)&out[(long)b0r * NE_ + n] = make_float4(o0x, o0y, o0z, o0w);
            *(float4*)&out[(long)b1r * NE_ + n] = make_float4(o1x, o1y, o1z, o1w);
        }
    }
}

// ---------------- launch ----------------
extern "C" void kernel_launch(void* const* d_in, const int* in_sizes, int n_in,
                              void* d_out, int out_size) {
    const int*   e1_idx = (const int*)  d_in[0];
    const int*   r_idx  = (const int*)  d_in[1];
    const float* E      = (const float*)d_in[2];
    const float* R      = (const float*)d_in[3];
    const float* W      = (const float*)d_in[4];
    const float* lits   = (const float*)d_in[5];
    const float* c      = (const float*)d_in[6];
    const float* var_l  = (const float*)d_in[7];
    const float* nf     = (const float*)d_in[8];
    const float* g0     = (const float*)d_in[9];
    const float* b0     = (const float*)d_in[10];
    const float* g1     = (const float*)d_in[11];
    const float* b1     = (const float*)d_in[12];
    float* out = (float*)d_out;

    k_prep<<<28, 256>>>(e1_idx, r_idx, E, R, lits, c, var_l, nf, g0, b0);
    k_wgemm<<<dim3(2, KSPLIT), 256>>>(W);
    k_bn1f<<<13, 512>>>(g1, b1);
    k_score<<<NE_ / 64, 256>>>(E, lits, out);
}